// round 13
// baseline (speedup 1.0000x reference)
#include <cuda_runtime.h>
#include <cstdint>

// ---------------- problem constants ----------------
constexpr int F = 64;
constexpr int H = 128;
constexpr int O = 512;
constexpr int K = F * H;            // 8192
constexpr int MT = 128;             // CTA M tile
constexpr int NT = 128;             // CTA N tile
constexpr int KB = 16;              // K per pipeline stage
constexpr int NSTAGES = K / KB;     // 512
constexpr int THREADS = 256;        // 8 warps: 4 (m) x 2 (n), warp tile 32x64

// ---------------- smem layout (float offsets) ----------------
constexpr int XS        = 0;                 // x tile [F][129] (padded)
constexpr int XS_STRIDE = 129;
constexpr int BSUM      = XS + F * XS_STRIDE;        // 8256, 128 floats
constexpr int AS        = 8384;                      // A: 2 bufs x [128][20]
constexpr int AS_STRIDE = 20;                        // KB=16 + 4 pad (conflict-free)
constexpr int AS_SZ     = MT * AS_STRIDE;            // 2560
constexpr int BBS       = AS + 2 * AS_SZ;            // 13504, B: 2 bufs x [16][136]
constexpr int BS_STRIDE = 136;                       // 128 + 8 pad (conflict-free)
constexpr int BS_SZ     = KB * BS_STRIDE;            // 2176
constexpr int SMEM_FLOATS = BBS + 2 * BS_SZ;         // 17856
constexpr int SMEM_BYTES  = SMEM_FLOATS * 4;         // 71424

// ---------------- helpers ----------------
__device__ __forceinline__ uint32_t smem_u32(const void* p) {
    uint32_t a;
    asm("{ .reg .u64 t; cvta.to.shared.u64 t, %1; cvt.u32.u64 %0, t; }" : "=r"(a) : "l"(p));
    return a;
}

// round fp32 -> tf32 (rna) keeping it in a 32-bit reg
__device__ __forceinline__ uint32_t tf32u(float a) {
    uint32_t d;
    asm("cvt.rna.tf32.f32 %0, %1;" : "=r"(d) : "f"(a));
    return d;
}
__device__ __forceinline__ float to_tf32(float a) {
    return __uint_as_float(tf32u(a));
}

// elu with tf32 rounding (operand for the tf32 MMA)
__device__ __forceinline__ float elu_tf32(float z) {
    float zm = fminf(z, 0.0f);
    float zp = fmaxf(z, 0.0f);
    float e  = __expf(zm);           // z>0 -> e=1
    return to_tf32(e + (zp - 1.0f)); // z>0 -> z ; z<=0 -> exp(z)-1
}

// m16n8k8 tf32 mma.sync (sm_80-era; valid on compute_103 — no tcgen05/'a' feature needed)
__device__ __forceinline__ void mma8(float* c, const uint32_t* a, uint32_t b0, uint32_t b1) {
    asm volatile(
        "mma.sync.aligned.m16n8k8.row.col.f32.tf32.tf32.f32 "
        "{%0,%1,%2,%3},{%4,%5,%6,%7},{%8,%9},{%0,%1,%2,%3};"
        : "+f"(c[0]), "+f"(c[1]), "+f"(c[2]), "+f"(c[3])
        : "r"(a[0]), "r"(a[1]), "r"(a[2]), "r"(a[3]), "r"(b0), "r"(b1));
}

// ---------------- main kernel ----------------
__global__ void __launch_bounds__(THREADS, 2)
mlp_gemm_kernel(const float* __restrict__ x, const float* __restrict__ W1,
                const float* __restrict__ b1, const float* __restrict__ W2,
                const float* __restrict__ b2, float* __restrict__ out)
{
    extern __shared__ float sm[];
    const uint32_t smu = smem_u32(sm);
    const int tid = threadIdx.x;
    const int wid = tid >> 5, lid = tid & 31;
    const int tg  = lid >> 2, tq = lid & 3;   // fragment geometry
    const int wm  = wid & 3,  wn = wid >> 2;  // warp grid 4x2
    const int m0  = blockIdx.x * MT;
    const int n0  = blockIdx.y * NT;

    // x tile: xs[f][r] = x[m0+r, f]  (coalesced read, padded-conflict-free write)
    for (int idx = tid; idx < MT * F; idx += THREADS) {
        int r = idx >> 6, f = idx & 63;
        sm[XS + f * XS_STRIDE + r] = x[(size_t)(m0 + r) * F + f];
    }
    // bsum[c] = sum_f b2[f, n0+c]
    if (tid < NT) {
        float s = 0.0f;
        #pragma unroll 8
        for (int f = 0; f < F; f++) s += b2[(size_t)f * O + n0 + tid];
        sm[BSUM + tid] = s;
    }

    float acc[2][8][4];
    #pragma unroll
    for (int mb = 0; mb < 2; mb++)
        #pragma unroll
        for (int nb = 0; nb < 8; nb++)
            #pragma unroll
            for (int i = 0; i < 4; i++) acc[mb][nb][i] = 0.0f;

    // producer thread mapping
    const int ac = tid & 3;        // A: 4-col group within the 16-wide stage
    const int ar = tid >> 2;       // A: rows ar, ar+64

    // ---- stage producers ----
    auto produceB = [&](int s, int buf) {
        const int k0 = s * KB;
        int e = tid;
        #pragma unroll
        for (int i = 0; i < 2; i++, e += THREADS) {
            int k = e >> 5, nq = e & 31;                 // 16B chunk
            uint32_t dst = smu + (uint32_t)(BBS + buf * BS_SZ + k * BS_STRIDE + nq * 4) * 4u;
            const float* src = W2 + (size_t)(k0 + k) * O + n0 + nq * 4;
            asm volatile("cp.async.cg.shared.global [%0], [%1], 16;\n"
                         :: "r"(dst), "l"(src) : "memory");
        }
    };
    auto produceA = [&](int s, int buf) {
        const int f  = s >> 3;
        const int h0 = (s & 7) << 4;
        const float4 w4 = *(const float4*)(W1 + (size_t)f * H + h0 + ac * 4);
        const float4 c4 = *(const float4*)(b1 + (size_t)f * H + h0 + ac * 4);
        #pragma unroll
        for (int i = 0; i < 2; i++) {
            int r = ar + i * 64;
            float xv = sm[XS + f * XS_STRIDE + r];
            float4 av;
            av.x = elu_tf32(fmaf(xv, w4.x, c4.x));
            av.y = elu_tf32(fmaf(xv, w4.y, c4.y));
            av.z = elu_tf32(fmaf(xv, w4.z, c4.z));
            av.w = elu_tf32(fmaf(xv, w4.w, c4.w));
            *(float4*)&sm[AS + buf * AS_SZ + r * AS_STRIDE + ac * 4] = av;
        }
    };

    // prologue: stage 0
    produceB(0, 0);
    asm volatile("cp.async.commit_group;\n" ::: "memory");
    produceA(0, 0);

    #pragma unroll 1
    for (int s = 0; s < NSTAGES; s++) {
        const int buf = s & 1;
        asm volatile("cp.async.wait_group 0;\n" ::: "memory");
        __syncthreads();   // stage-s B & A visible; buf^1 free for reuse

        if (s + 1 < NSTAGES) {
            produceB(s + 1, buf ^ 1);
            asm volatile("cp.async.commit_group;\n" ::: "memory");
            produceA(s + 1, buf ^ 1);
        }

        // ---- consume stage s: 2 k8-steps x (2 m16) x (8 n8) mmas ----
        const float* As = sm + AS + buf * AS_SZ;
        const float* Bs = sm + BBS + buf * BS_SZ;
        #pragma unroll
        for (int kk = 0; kk < KB; kk += 8) {
            uint32_t a[2][4];
            #pragma unroll
            for (int mb = 0; mb < 2; mb++) {
                const float* ap = As + (wm * 32 + mb * 16 + tg) * AS_STRIDE + kk + tq;
                a[mb][0] = __float_as_uint(ap[0]);
                a[mb][1] = __float_as_uint(ap[8 * AS_STRIDE]);
                a[mb][2] = __float_as_uint(ap[4]);
                a[mb][3] = __float_as_uint(ap[8 * AS_STRIDE + 4]);
            }
            #pragma unroll
            for (int nb = 0; nb < 8; nb++) {
                const float* bp = Bs + (kk + tq) * BS_STRIDE + wn * 64 + nb * 8 + tg;
                uint32_t b0 = tf32u(bp[0]);
                uint32_t b1r = tf32u(bp[4 * BS_STRIDE]);
                mma8(acc[0][nb], a[0], b0, b1r);
                mma8(acc[1][nb], a[1], b0, b1r);
            }
        }
    }

    // ---- epilogue: add summed bias, scale by 1/sqrt(F)=0.125, store ----
    #pragma unroll
    for (int mb = 0; mb < 2; mb++) {
        const int row = m0 + wm * 32 + mb * 16 + tg;
        #pragma unroll
        for (int nb = 0; nb < 8; nb++) {
            const int cl = wn * 64 + nb * 8 + tq * 2;   // local col
            const float bs0 = sm[BSUM + cl];
            const float bs1 = sm[BSUM + cl + 1];
            float2 v0, v1;
            v0.x = (acc[mb][nb][0] + bs0) * 0.125f;
            v0.y = (acc[mb][nb][1] + bs1) * 0.125f;
            v1.x = (acc[mb][nb][2] + bs0) * 0.125f;
            v1.y = (acc[mb][nb][3] + bs1) * 0.125f;
            *(float2*)(out + (size_t)row * O + n0 + cl)       = v0;
            *(float2*)(out + (size_t)(row + 8) * O + n0 + cl) = v1;
        }
    }
}

// ---------------- launch ----------------
extern "C" void kernel_launch(void* const* d_in, const int* in_sizes, int n_in,
                              void* d_out, int out_size) {
    const float* x  = (const float*)d_in[0];   // [16384, 64]
    const float* W1 = (const float*)d_in[1];   // [64, 128]
    const float* b1 = (const float*)d_in[2];   // [64, 128]
    const float* W2 = (const float*)d_in[3];   // [64, 128, 512] == [K, O]
    const float* b2 = (const float*)d_in[4];   // [64, 512]
    float* out = (float*)d_out;                // [16384, 512]

    cudaFuncSetAttribute(mlp_gemm_kernel,
                         cudaFuncAttributeMaxDynamicSharedMemorySize, SMEM_BYTES);

    dim3 grid(16384 / MT, O / NT);             // 128 x 4
    mlp_gemm_kernel<<<grid, THREADS, SMEM_BYTES>>>(x, W1, b1, W2, b2, out);
}